// round 2
// baseline (speedup 1.0000x reference)
#include <cuda_runtime.h>
#include <stdint.h>

// Problem constants
#define TOT_E      10
#define SPIKE_E0   8
#define DIN        512
#define DHID       1024
#define DOUT       256
#define BTOK       32768
#define TSPK       16
#define NPAIRS     (BTOK * 2)
#define MAX_TILES  522
#define BM 128
#define BN 128
#define BK 32

#define AS_STRIDE 36      // BK+4 floats, 144B rows (16B aligned, conflict-free A frags)
#define BS_STRIDE 136     // BN+8 floats, 544B rows (bank shift 8 -> conflict-free B frags)
#define AS_STAGE_F (BM * AS_STRIDE)            // floats per A stage
#define BS_STAGE_F (BK * BS_STRIDE)            // floats per B stage
#define SMEM_FLOATS (2 * AS_STAGE_F + 2 * BS_STAGE_F)
#define SMEM_BYTES (SMEM_FLOATS * 4)           // 71680 B

// ----------------------------------------------------------------------------
// Device scratch
// ----------------------------------------------------------------------------
__device__ float g_h[(size_t)NPAIRS * DHID];
__device__ float g_z[(size_t)NPAIRS * DOUT];
__device__ int   g_perm[NPAIRS];
__device__ float g_wgt[NPAIRS];
__device__ int   g_rowOf[NPAIRS];
__device__ int   g_topk_e[NPAIRS];
__device__ float g_topk_w[NPAIRS];
__device__ int   g_counts[TOT_E];
__device__ int   g_offsets[TOT_E + 1];
__device__ int   g_cursor[TOT_E];
__device__ int   g_tile_e[MAX_TILES];
__device__ int   g_tile_r0[MAX_TILES];
__device__ int   g_tile_r1[MAX_TILES];
__device__ int   g_num_tiles;

// ----------------------------------------------------------------------------
// Helpers
// ----------------------------------------------------------------------------
__device__ __forceinline__ uint32_t f2tf32(float f) {
    uint32_t r;
    asm("cvt.rna.tf32.f32 %0, %1;" : "=r"(r) : "f"(f));
    return r;
}

__device__ __forceinline__ void mma_tf32(float* c, const uint32_t* a, const uint32_t* b) {
    asm volatile(
        "mma.sync.aligned.m16n8k8.row.col.f32.tf32.tf32.f32 "
        "{%0,%1,%2,%3}, {%4,%5,%6,%7}, {%8,%9}, {%0,%1,%2,%3};"
        : "+f"(c[0]), "+f"(c[1]), "+f"(c[2]), "+f"(c[3])
        : "r"(a[0]), "r"(a[1]), "r"(a[2]), "r"(a[3]),
          "r"(b[0]), "r"(b[1]));
}

__device__ __forceinline__ uint32_t smem_u32(const void* p) {
    return (uint32_t)__cvta_generic_to_shared(p);
}

__device__ __forceinline__ void cp16(uint32_t dst, const void* src, int sz) {
    asm volatile("cp.async.cg.shared.global [%0], [%1], 16, %2;"
                 :: "r"(dst), "l"(src), "r"(sz));
}
__device__ __forceinline__ void cp_commit() {
    asm volatile("cp.async.commit_group;");
}
__device__ __forceinline__ void cp_wait0() {
    asm volatile("cp.async.wait_group 0;");
}

// ----------------------------------------------------------------------------
// 0. zero the histogram (graph replays reuse globals)
// ----------------------------------------------------------------------------
__global__ void zero_kernel() {
    if (threadIdx.x < TOT_E) g_counts[threadIdx.x] = 0;
}

// ----------------------------------------------------------------------------
// 1. Router: one warp per token
// ----------------------------------------------------------------------------
__global__ void router_kernel(const float* __restrict__ x,
                              const float* __restrict__ spike,
                              const float* __restrict__ Wr,
                              const float* __restrict__ br) {
    int warp = (blockIdx.x * blockDim.x + threadIdx.x) >> 5;
    int lane = threadIdx.x & 31;
    if (warp >= BTOK) return;
    const float* xr = x + (size_t)warp * DIN;

    float acc[TOT_E];
#pragma unroll
    for (int e = 0; e < TOT_E; e++) acc[e] = 0.f;

    for (int k = lane; k < DIN; k += 32) {
        float xv = xr[k];
        const float* wrow = Wr + k * TOT_E;
#pragma unroll
        for (int e = 0; e < TOT_E; e++) acc[e] += xv * wrow[e];
    }
#pragma unroll
    for (int e = 0; e < TOT_E; e++) {
#pragma unroll
        for (int off = 16; off; off >>= 1)
            acc[e] += __shfl_xor_sync(0xffffffffu, acc[e], off);
    }
    float sp = (lane < TSPK) ? spike[warp * TSPK + lane] : 0.f;
#pragma unroll
    for (int off = 16; off; off >>= 1)
        sp += __shfl_xor_sync(0xffffffffu, sp, off);

    if (lane == 0) {
        float avg = sp * (1.f / TSPK);
        float lg[TOT_E];
#pragma unroll
        for (int e = 0; e < TOT_E; e++)
            lg[e] = acc[e] + br[e] + (e >= SPIKE_E0 ? avg : 0.f);
        float m = lg[0];
#pragma unroll
        for (int e = 1; e < TOT_E; e++) m = fmaxf(m, lg[e]);
        float p[TOT_E];
        float Z = 0.f;
#pragma unroll
        for (int e = 0; e < TOT_E; e++) { p[e] = expf(lg[e] - m); Z += p[e]; }
        float invZ = 1.f / Z;
#pragma unroll
        for (int e = 0; e < TOT_E; e++) p[e] *= invZ;

        int e0 = 0;
#pragma unroll
        for (int e = 1; e < TOT_E; e++) if (p[e] > p[e0]) e0 = e;
        int e1 = (e0 == 0) ? 1 : 0;
#pragma unroll
        for (int e = 0; e < TOT_E; e++)
            if (e != e0 && p[e] > p[e1]) e1 = e;

        float s = p[e0] + p[e1] + 1e-9f;
        g_topk_e[2 * warp + 0] = e0;
        g_topk_e[2 * warp + 1] = e1;
        g_topk_w[2 * warp + 0] = p[e0] / s;
        g_topk_w[2 * warp + 1] = p[e1] / s;
        atomicAdd(&g_counts[e0], 1);
        atomicAdd(&g_counts[e1], 1);
    }
}

// ----------------------------------------------------------------------------
// 2. Prefix sums + tile table
// ----------------------------------------------------------------------------
__global__ void offsets_kernel() {
    int off = 0;
    for (int e = 0; e < TOT_E; e++) {
        g_offsets[e] = off;
        g_cursor[e]  = off;
        off += g_counts[e];
    }
    g_offsets[TOT_E] = off;
    int nt = 0;
    for (int e = 0; e < TOT_E; e++) {
        int n  = g_counts[e];
        int r0 = g_offsets[e];
        for (int t = 0; t < n; t += BM) {
            g_tile_e[nt]  = e;
            g_tile_r0[nt] = r0 + t;
            int r1 = r0 + t + BM;
            int re = r0 + n;
            g_tile_r1[nt] = r1 < re ? r1 : re;
            nt++;
        }
    }
    g_num_tiles = nt;
}

// ----------------------------------------------------------------------------
// 3. Scatter pairs: block-local aggregation, then one global atomic per expert
// ----------------------------------------------------------------------------
__global__ void scatter_kernel() {
    __shared__ int cnt[TOT_E];
    __shared__ int base[TOT_E];
    int tid = threadIdx.x;
    if (tid < TOT_E) cnt[tid] = 0;
    __syncthreads();
    int i = blockIdx.x * blockDim.x + tid;
    int e = g_topk_e[i];
    int loc = atomicAdd(&cnt[e], 1);
    __syncthreads();
    if (tid < TOT_E) base[tid] = atomicAdd(&g_cursor[tid], cnt[tid]);
    __syncthreads();
    int pos = base[e] + loc;
    g_perm[pos] = i >> 1;
    g_wgt[pos]  = g_topk_w[i];
    g_rowOf[i]  = pos;
}

// ----------------------------------------------------------------------------
// 4. Grouped GEMM, cp.async double-buffered, TF32 mma.sync
//    BM=128 BN=128 BK=32, 8 warps (2x4), warp tile 64x32
// ----------------------------------------------------------------------------
template<int KDIM, int NDIM, bool GATHER, bool RELU, bool SCALE>
__global__ __launch_bounds__(256, 2)
void gemm_kernel(const float* __restrict__ Asrc,
                 const float* __restrict__ W,
                 const float* __restrict__ bias) {
    extern __shared__ float smem[];
    float (*As)[BM][AS_STRIDE] = (float (*)[BM][AS_STRIDE])smem;
    float (*Bs)[BK][BS_STRIDE] = (float (*)[BK][BS_STRIDE])(smem + 2 * AS_STAGE_F);

    int bt = blockIdx.x;
    if (bt >= g_num_tiles) return;
    int e  = g_tile_e[bt];
    int r0 = g_tile_r0[bt];
    int r1 = g_tile_r1[bt];
    int n0 = blockIdx.y * BN;

    const float* Aptr = GATHER ? Asrc : g_h;
    float*       Out  = RELU ? g_h : g_z;
    const float* Wexp = W + (size_t)e * KDIM * NDIM;
    const float* be   = bias + e * NDIM;

    int tid  = threadIdx.x;
    int lane = tid & 31;
    int wid  = tid >> 5;
    int gidl = lane >> 2;
    int tg   = lane & 3;
    int wm   = (wid >> 2) * 64;
    int wn   = (wid & 3) * 32;

    // ---- staging thread maps ----
    // A: 2 threads per row, each 16 floats (4x 16B)
    int amrow = tid >> 1;
    int acol  = (tid & 1) * 16;
    int ra = r0 + amrow;
    bool av = (ra < r1);
    const float* abase;
    if (GATHER) abase = Aptr + (av ? (size_t)g_perm[ra] * KDIM : 0) + acol;
    else        abase = Aptr + (av ? (size_t)ra * KDIM : 0) + acol;
    int asz = av ? 16 : 0;
    uint32_t aDst0 = smem_u32(&As[0][amrow][acol]);

    // B: 8 threads per k-row, each 16 floats
    int bkrow = tid >> 3;
    int bcol  = (tid & 7) * 16;
    const float* bbase = Wexp + (size_t)bkrow * NDIM + n0 + bcol;
    uint32_t bDst0 = smem_u32(&Bs[0][bkrow][bcol]);

    float acc[4][4][4];
#pragma unroll
    for (int a = 0; a < 4; a++)
#pragma unroll
        for (int b = 0; b < 4; b++)
#pragma unroll
            for (int c = 0; c < 4; c++) acc[a][b][c] = 0.f;

    const int NKT = KDIM / BK;

    // ---- prologue: stage 0 ----
    {
        const float* as = abase;
        uint32_t ad = aDst0;
#pragma unroll
        for (int c = 0; c < 4; c++) cp16(ad + c * 16, as + c * 4, asz);
        const float* bs = bbase;
        uint32_t bd = bDst0;
#pragma unroll
        for (int c = 0; c < 4; c++) cp16(bd + c * 16, bs + c * 4, 16);
        cp_commit();
    }

    for (int kt = 0; kt < NKT; kt++) {
        cp_wait0();
        __syncthreads();
        int cur = kt & 1;

        if (kt + 1 < NKT) {
            int nxt = (kt + 1) & 1;
            int ko  = (kt + 1) * BK;
            const float* as = abase + ko;
            uint32_t ad = aDst0 + nxt * (AS_STAGE_F * 4);
#pragma unroll
            for (int c = 0; c < 4; c++) cp16(ad + c * 16, as + c * 4, asz);
            const float* bs = bbase + (size_t)ko * NDIM;
            uint32_t bd = bDst0 + nxt * (BS_STAGE_F * 4);
#pragma unroll
            for (int c = 0; c < 4; c++) cp16(bd + c * 16, bs + c * 4, 16);
            cp_commit();
        }

        // ---- compute current stage ----
#pragma unroll
        for (int kk = 0; kk < BK; kk += 8) {
            uint32_t af[4][4], bf[4][2];
#pragma unroll
            for (int mi = 0; mi < 4; mi++) {
                int m = wm + mi * 16;
                af[mi][0] = f2tf32(As[cur][m + gidl    ][kk + tg    ]);
                af[mi][1] = f2tf32(As[cur][m + gidl + 8][kk + tg    ]);
                af[mi][2] = f2tf32(As[cur][m + gidl    ][kk + tg + 4]);
                af[mi][3] = f2tf32(As[cur][m + gidl + 8][kk + tg + 4]);
            }
#pragma unroll
            for (int ni = 0; ni < 4; ni++) {
                int n = wn + ni * 8;
                bf[ni][0] = f2tf32(Bs[cur][kk + tg    ][n + gidl]);
                bf[ni][1] = f2tf32(Bs[cur][kk + tg + 4][n + gidl]);
            }
#pragma unroll
            for (int mi = 0; mi < 4; mi++)
#pragma unroll
                for (int ni = 0; ni < 4; ni++)
                    mma_tf32(acc[mi][ni], af[mi], bf[ni]);
        }
    }

    // ---- epilogue ----
#pragma unroll
    for (int mi = 0; mi < 4; mi++) {
#pragma unroll
        for (int ri = 0; ri < 2; ri++) {
            int r = r0 + wm + mi * 16 + gidl + ri * 8;
            if (r >= r1) continue;
            float sc = SCALE ? g_wgt[r] : 1.f;
            float* orow = Out + (size_t)r * NDIM;
#pragma unroll
            for (int ni = 0; ni < 4; ni++) {
                int c  = n0 + wn + ni * 8 + 2 * tg;
                float v0 = acc[mi][ni][ri * 2 + 0] + be[c];
                float v1 = acc[mi][ni][ri * 2 + 1] + be[c + 1];
                if (RELU) { v0 = fmaxf(v0, 0.f); v1 = fmaxf(v1, 0.f); }
                if (SCALE) { v0 *= sc; v1 *= sc; }
                float2 v2 = make_float2(v0, v1);
                *reinterpret_cast<float2*>(orow + c) = v2;
            }
        }
    }
}

// ----------------------------------------------------------------------------
// 5. Combine (float4)
// ----------------------------------------------------------------------------
__global__ void combine_kernel(float4* __restrict__ out) {
    int i = blockIdx.x * blockDim.x + threadIdx.x;   // over BTOK*DOUT/4
    const int C4 = DOUT / 4;
    int t = i / C4;
    int c = i % C4;
    int ra = g_rowOf[2 * t + 0];
    int rb = g_rowOf[2 * t + 1];
    const float4* z4 = (const float4*)g_z;
    float4 a = z4[(size_t)ra * C4 + c];
    float4 b = z4[(size_t)rb * C4 + c];
    out[i] = make_float4(a.x + b.x, a.y + b.y, a.z + b.z, a.w + b.w);
}

// ----------------------------------------------------------------------------
// Launch
// ----------------------------------------------------------------------------
extern "C" void kernel_launch(void* const* d_in, const int* in_sizes, int n_in,
                              void* d_out, int out_size) {
    const float* x     = (const float*)d_in[0];
    const float* spike = (const float*)d_in[1];
    const float* Wr    = (const float*)d_in[2];
    const float* br    = (const float*)d_in[3];
    const float* W1    = (const float*)d_in[4];
    const float* b1    = (const float*)d_in[5];
    const float* W2    = (const float*)d_in[6];
    const float* b2    = (const float*)d_in[7];
    float* out = (float*)d_out;

    cudaFuncSetAttribute(gemm_kernel<DIN, DHID, true, true, false>,
                         cudaFuncAttributeMaxDynamicSharedMemorySize, SMEM_BYTES);
    cudaFuncSetAttribute(gemm_kernel<DHID, DOUT, false, false, true>,
                         cudaFuncAttributeMaxDynamicSharedMemorySize, SMEM_BYTES);

    zero_kernel<<<1, 32>>>();
    router_kernel<<<BTOK / 8, 256>>>(x, spike, Wr, br);
    offsets_kernel<<<1, 1>>>();
    scatter_kernel<<<NPAIRS / 256, 256>>>();
    gemm_kernel<DIN, DHID, true, true, false>
        <<<dim3(MAX_TILES, DHID / BN), 256, SMEM_BYTES>>>(x, W1, b1);
    gemm_kernel<DHID, DOUT, false, false, true>
        <<<dim3(MAX_TILES, DOUT / BN), 256, SMEM_BYTES>>>(nullptr, W2, b2);
    combine_kernel<<<(BTOK * DOUT / 4) / 256, 256>>>((float4*)out);
}

// round 6
// speedup vs baseline: 1.5657x; 1.5657x over previous
#include <cuda_runtime.h>
#include <cuda_fp16.h>
#include <stdint.h>

// ---------------- problem constants ----------------
#define TOT_E      10
#define SPIKE_E0   8
#define DIN        512
#define DHID       1024
#define DOUT       256
#define BTOK       32768
#define TSPK       16
#define NPAIRS     (BTOK * 2)
#define BM 128
#define BN 128
#define BKH 32                             // K halves per slab
#define MAX_TILES  (NPAIRS / BM + TOT_E)   // 522
#define SROW 40                            // smem row stride in halves (80 B)

// ---------------- device scratch (referenced ONLY in device code) ----------
__device__ __half g_h[(size_t)NPAIRS * DHID];
__device__ float  g_z[(size_t)NPAIRS * DOUT];
__device__ __half g_xh[(size_t)BTOK * DIN];
__device__ __half g_W1t[(size_t)TOT_E * DIN * DHID];   // [E][N=DHID][K=DIN]
__device__ __half g_W2t[(size_t)TOT_E * DHID * DOUT];  // [E][N=DOUT][K=DHID]
__device__ int    g_perm[NPAIRS];
__device__ float  g_wgt[NPAIRS];
__device__ int    g_rowOf[NPAIRS];
__device__ int    g_topk_e[NPAIRS];
__device__ float  g_topk_w[NPAIRS];
__device__ int    g_counts[TOT_E];
__device__ int    g_cursor[TOT_E];
__device__ int    g_tile_e[MAX_TILES];
__device__ int    g_tile_r0[MAX_TILES];
__device__ int    g_tile_r1[MAX_TILES];
__device__ int    g_num_tiles;

// ---------------- helpers ----------------
__device__ __forceinline__ void mma_f16(float* c, const uint32_t* a, const uint32_t* b) {
    asm volatile(
        "mma.sync.aligned.m16n8k16.row.col.f32.f16.f16.f32 "
        "{%0,%1,%2,%3}, {%4,%5,%6,%7}, {%8,%9}, {%0,%1,%2,%3};"
        : "+f"(c[0]), "+f"(c[1]), "+f"(c[2]), "+f"(c[3])
        : "r"(a[0]), "r"(a[1]), "r"(a[2]), "r"(a[3]),
          "r"(b[0]), "r"(b[1]));
}

// ---------------- small kernels ----------------
__global__ void zero_kernel() {
    if (threadIdx.x < TOT_E) g_counts[threadIdx.x] = 0;
}

__global__ void router_kernel(const float* __restrict__ x,
                              const float* __restrict__ spike,
                              const float* __restrict__ Wr,
                              const float* __restrict__ br) {
    int warp = (blockIdx.x * blockDim.x + threadIdx.x) >> 5;
    int lane = threadIdx.x & 31;
    if (warp >= BTOK) return;
    const float* xr = x + (size_t)warp * DIN;

    float acc[TOT_E];
#pragma unroll
    for (int e = 0; e < TOT_E; e++) acc[e] = 0.f;
    for (int k = lane; k < DIN; k += 32) {
        float xv = xr[k];
        const float* wrow = Wr + k * TOT_E;
#pragma unroll
        for (int e = 0; e < TOT_E; e++) acc[e] += xv * wrow[e];
    }
#pragma unroll
    for (int e = 0; e < TOT_E; e++)
#pragma unroll
        for (int off = 16; off; off >>= 1)
            acc[e] += __shfl_xor_sync(0xffffffffu, acc[e], off);
    float sp = (lane < TSPK) ? spike[warp * TSPK + lane] : 0.f;
#pragma unroll
    for (int off = 16; off; off >>= 1)
        sp += __shfl_xor_sync(0xffffffffu, sp, off);

    if (lane == 0) {
        float avg = sp * (1.f / TSPK);
        float lg[TOT_E];
#pragma unroll
        for (int e = 0; e < TOT_E; e++)
            lg[e] = acc[e] + br[e] + (e >= SPIKE_E0 ? avg : 0.f);
        float m = lg[0];
#pragma unroll
        for (int e = 1; e < TOT_E; e++) m = fmaxf(m, lg[e]);
        float p[TOT_E]; float Z = 0.f;
#pragma unroll
        for (int e = 0; e < TOT_E; e++) { p[e] = expf(lg[e] - m); Z += p[e]; }
        float invZ = 1.f / Z;
#pragma unroll
        for (int e = 0; e < TOT_E; e++) p[e] *= invZ;
        int e0 = 0;
#pragma unroll
        for (int e = 1; e < TOT_E; e++) if (p[e] > p[e0]) e0 = e;
        int e1 = (e0 == 0) ? 1 : 0;
#pragma unroll
        for (int e = 0; e < TOT_E; e++)
            if (e != e0 && p[e] > p[e1]) e1 = e;
        float s = p[e0] + p[e1] + 1e-9f;
        g_topk_e[2 * warp + 0] = e0;
        g_topk_e[2 * warp + 1] = e1;
        g_topk_w[2 * warp + 0] = p[e0] / s;
        g_topk_w[2 * warp + 1] = p[e1] / s;
        atomicAdd(&g_counts[e0], 1);
        atomicAdd(&g_counts[e1], 1);
    }
}

__global__ void offsets_kernel() {
    int off = 0;
    int offs[TOT_E];
    for (int e = 0; e < TOT_E; e++) {
        offs[e] = off;
        g_cursor[e] = off;
        off += g_counts[e];
    }
    int nt = 0;
    for (int e = 0; e < TOT_E; e++) {
        int n = g_counts[e];
        int r0 = offs[e];
        for (int t = 0; t < n; t += BM) {
            g_tile_e[nt] = e;
            g_tile_r0[nt] = r0 + t;
            int r1 = r0 + t + BM;
            int re = r0 + n;
            g_tile_r1[nt] = r1 < re ? r1 : re;
            nt++;
        }
    }
    g_num_tiles = nt;
}

__global__ void scatter_kernel() {
    __shared__ int cnt[TOT_E];
    __shared__ int base[TOT_E];
    int tid = threadIdx.x;
    if (tid < TOT_E) cnt[tid] = 0;
    __syncthreads();
    int i = blockIdx.x * blockDim.x + tid;
    int e = g_topk_e[i];
    int loc = atomicAdd(&cnt[e], 1);
    __syncthreads();
    if (tid < TOT_E) base[tid] = atomicAdd(&g_cursor[tid], cnt[tid]);
    __syncthreads();
    int pos = base[e] + loc;
    g_perm[pos] = i >> 1;
    g_wgt[pos]  = g_topk_w[i];
    g_rowOf[i]  = pos;
}

// x (fp32) -> g_xh (half)
__global__ void cvtx_kernel(const float4* __restrict__ x) {
    int i = blockIdx.x * blockDim.x + threadIdx.x;
    float4 v = x[i];
    ((__half2*)g_xh)[2 * i]     = __floats2half2_rn(v.x, v.y);
    ((__half2*)g_xh)[2 * i + 1] = __floats2half2_rn(v.z, v.w);
}

// W[e][K][N] fp32 -> Wt[e][N][K] half   (destination chosen in DEVICE code)
template<bool FIRST>
__global__ void transpose_kernel(const float* __restrict__ W, int K, int N) {
    __half* Wt = FIRST ? g_W1t : g_W2t;
    __shared__ float t[32][33];
    int e = blockIdx.z;
    const float* Ws = W + (size_t)e * K * N;
    __half* Wd = Wt + (size_t)e * K * N;
    int k0 = blockIdx.x * 32, n0 = blockIdx.y * 32;
    int tx = threadIdx.x, ty = threadIdx.y;   // 32 x 8
#pragma unroll
    for (int i = 0; i < 32; i += 8)
        t[ty + i][tx] = Ws[(size_t)(k0 + ty + i) * N + n0 + tx];
    __syncthreads();
#pragma unroll
    for (int i = 0; i < 32; i += 8)
        Wd[(size_t)(n0 + ty + i) * K + k0 + tx] = __float2half_rn(t[tx][ty + i]);
}

// ---------------- fp16 grouped GEMM (R1 skeleton, m16n8k16) ----------------
// BM=128 BN=128 BKH=32, 8 warps (2x4), warp tile 64x32.
// FIRST: A = gathered g_xh, B = g_W1t, out = relu -> g_h
// !FIRST: A = g_h rows,     B = g_W2t, out = *wgt -> g_z
template<bool FIRST>
__global__ __launch_bounds__(256, 2)
void gemm_kernel(const float* __restrict__ bias) {
    const int KDIM = FIRST ? DIN : DHID;
    const int NDIM = FIRST ? DHID : DOUT;
    const __half* A0 = FIRST ? g_xh : g_h;
    const __half* Bt = FIRST ? g_W1t : g_W2t;

    __shared__ __half As[BM][SROW];
    __shared__ __half Bs[BN][SROW];

    int bt = blockIdx.x;
    if (bt >= g_num_tiles) return;
    int e  = g_tile_e[bt];
    int r0 = g_tile_r0[bt];
    int r1 = g_tile_r1[bt];
    int n0 = blockIdx.y * BN;

    const __half* Bexp = Bt + (size_t)e * NDIM * KDIM;

    int tid  = threadIdx.x;
    int lane = tid & 31;
    int wid  = tid >> 5;
    int gidl = lane >> 2;
    int tg   = lane & 3;
    int wm   = (wid >> 2) * 64;
    int wn   = (wid & 3) * 32;

    // staging: 2 threads per row, each 16 halves (two uint4)
    int srow = tid >> 1;
    int scol = (tid & 1) * 16;
    int ra = r0 + srow;
    bool av = ra < r1;
    const __half* aRow;
    if (FIRST) aRow = A0 + (av ? (size_t)g_perm[ra] * KDIM : 0) + scol;
    else       aRow = A0 + (av ? (size_t)ra * KDIM : 0) + scol;
    const __half* bRow = Bexp + (size_t)(n0 + srow) * KDIM + scol;

    float acc[4][4][4];
#pragma unroll
    for (int a = 0; a < 4; a++)
#pragma unroll
        for (int b = 0; b < 4; b++)
#pragma unroll
            for (int c = 0; c < 4; c++) acc[a][b][c] = 0.f;

    const int NC = KDIM / BKH;

    for (int c = 0; c < NC; c++) {
        // ---- stage slab c ----
        {
            uint4 va0 = make_uint4(0, 0, 0, 0), va1 = va0;
            if (av) {
                const uint4* s = (const uint4*)(aRow + c * BKH);
                va0 = s[0]; va1 = s[1];
            }
            *(uint4*)&As[srow][scol]     = va0;
            *(uint4*)&As[srow][scol + 8] = va1;
            const uint4* sb = (const uint4*)(bRow + c * BKH);
            uint4 vb0 = sb[0], vb1 = sb[1];
            *(uint4*)&Bs[srow][scol]     = vb0;
            *(uint4*)&Bs[srow][scol + 8] = vb1;
        }
        __syncthreads();

        // ---- compute: two k16 steps ----
#pragma unroll
        for (int kk = 0; kk < BKH; kk += 16) {
            uint32_t af[4][4], bf[4][2];
#pragma unroll
            for (int mi = 0; mi < 4; mi++) {
                int m = wm + mi * 16;
                af[mi][0] = *(const uint32_t*)&As[m + gidl    ][kk + 2 * tg    ];
                af[mi][1] = *(const uint32_t*)&As[m + gidl + 8][kk + 2 * tg    ];
                af[mi][2] = *(const uint32_t*)&As[m + gidl    ][kk + 2 * tg + 8];
                af[mi][3] = *(const uint32_t*)&As[m + gidl + 8][kk + 2 * tg + 8];
            }
#pragma unroll
            for (int ni = 0; ni < 4; ni++) {
                int n = wn + ni * 8 + gidl;
                bf[ni][0] = *(const uint32_t*)&Bs[n][kk + 2 * tg    ];
                bf[ni][1] = *(const uint32_t*)&Bs[n][kk + 2 * tg + 8];
            }
#pragma unroll
            for (int mi = 0; mi < 4; mi++)
#pragma unroll
                for (int ni = 0; ni < 4; ni++)
                    mma_f16(acc[mi][ni], af[mi], bf[ni]);
        }
        __syncthreads();
    }

    // ---- epilogue ----
    const float* be = bias + (size_t)e * NDIM;
#pragma unroll
    for (int mi = 0; mi < 4; mi++) {
#pragma unroll
        for (int ri = 0; ri < 2; ri++) {
            int r = r0 + wm + mi * 16 + gidl + ri * 8;
            if (r >= r1) continue;
            float sc = FIRST ? 1.f : g_wgt[r];
#pragma unroll
            for (int ni = 0; ni < 4; ni++) {
                int cc = n0 + wn + ni * 8 + 2 * tg;
                float v0 = acc[mi][ni][ri * 2 + 0] + be[cc];
                float v1 = acc[mi][ni][ri * 2 + 1] + be[cc + 1];
                if (FIRST) {
                    v0 = fmaxf(v0, 0.f);
                    v1 = fmaxf(v1, 0.f);
                    *reinterpret_cast<__half2*>(g_h + (size_t)r * NDIM + cc) =
                        __floats2half2_rn(v0, v1);
                } else {
                    v0 *= sc; v1 *= sc;
                    *reinterpret_cast<float2*>(g_z + (size_t)r * NDIM + cc) =
                        make_float2(v0, v1);
                }
            }
        }
    }
}

// ---------------- combine ----------------
__global__ void combine_kernel(float4* __restrict__ out) {
    int i = blockIdx.x * blockDim.x + threadIdx.x;
    const int C4 = DOUT / 4;
    int t = i / C4;
    int c = i % C4;
    int ra = g_rowOf[2 * t + 0];
    int rb = g_rowOf[2 * t + 1];
    const float4* z4 = (const float4*)g_z;
    float4 a = z4[(size_t)ra * C4 + c];
    float4 b = z4[(size_t)rb * C4 + c];
    out[i] = make_float4(a.x + b.x, a.y + b.y, a.z + b.z, a.w + b.w);
}

// ---------------- launch (only harness pointers cross host/device) --------
extern "C" void kernel_launch(void* const* d_in, const int* in_sizes, int n_in,
                              void* d_out, int out_size) {
    const float* x     = (const float*)d_in[0];
    const float* spike = (const float*)d_in[1];
    const float* Wr    = (const float*)d_in[2];
    const float* br    = (const float*)d_in[3];
    const float* W1    = (const float*)d_in[4];
    const float* b1    = (const float*)d_in[5];
    const float* W2    = (const float*)d_in[6];
    const float* b2    = (const float*)d_in[7];
    float* out = (float*)d_out;

    zero_kernel<<<1, 32>>>();
    router_kernel<<<BTOK / 8, 256>>>(x, spike, Wr, br);
    offsets_kernel<<<1, 1>>>();
    scatter_kernel<<<NPAIRS / 256, 256>>>();
    cvtx_kernel<<<(BTOK * DIN / 4) / 256, 256>>>((const float4*)x);
    transpose_kernel<true><<<dim3(DIN / 32, DHID / 32, TOT_E), dim3(32, 8)>>>(W1, DIN, DHID);
    transpose_kernel<false><<<dim3(DHID / 32, DOUT / 32, TOT_E), dim3(32, 8)>>>(W2, DHID, DOUT);

    gemm_kernel<true><<<dim3(MAX_TILES, DHID / BN), 256>>>(b1);
    gemm_kernel<false><<<dim3(MAX_TILES, DOUT / BN), 256>>>(b2);

    combine_kernel<<<(BTOK * DOUT / 4) / 256, 256>>>((float4*)out);
}

// round 7
// speedup vs baseline: 1.8349x; 1.1720x over previous
#include <cuda_runtime.h>
#include <cuda_fp16.h>
#include <stdint.h>

// ---------------- problem constants ----------------
#define TOT_E      10
#define SPIKE_E0   8
#define DIN        512
#define DHID       1024
#define DOUT       256
#define BTOK       32768
#define TSPK       16
#define NPAIRS     (BTOK * 2)
#define BM 128
#define BN 128
#define BKH 32                             // K halves per slab
#define MAX_TILES  (NPAIRS / BM + TOT_E)   // 522
#define SROW 40                            // smem row stride in halves (80 B)

// ---------------- device scratch (device-code references only) ------------
__device__ __half g_h[(size_t)NPAIRS * DHID];
__device__ float  g_z[(size_t)NPAIRS * DOUT];
__device__ __half g_xh[(size_t)BTOK * DIN];
__device__ __half g_W1t[(size_t)TOT_E * DIN * DHID];   // [E][N=DHID][K=DIN]
__device__ __half g_W2t[(size_t)TOT_E * DHID * DOUT];  // [E][N=DOUT][K=DHID]
__device__ int    g_perm[NPAIRS];
__device__ float  g_wgt[NPAIRS];
__device__ int    g_rowOf[NPAIRS];
__device__ int    g_topk_e[NPAIRS];
__device__ float  g_topk_w[NPAIRS];
__device__ int    g_counts[TOT_E];
__device__ int    g_cursor[TOT_E];
__device__ int    g_tile_e[MAX_TILES];
__device__ int    g_tile_r0[MAX_TILES];
__device__ int    g_tile_r1[MAX_TILES];
__device__ int    g_num_tiles;

// ---------------- helpers ----------------
__device__ __forceinline__ void mma_f16(float* c, const uint32_t* a, const uint32_t* b) {
    asm volatile(
        "mma.sync.aligned.m16n8k16.row.col.f32.f16.f16.f32 "
        "{%0,%1,%2,%3}, {%4,%5,%6,%7}, {%8,%9}, {%0,%1,%2,%3};"
        : "+f"(c[0]), "+f"(c[1]), "+f"(c[2]), "+f"(c[3])
        : "r"(a[0]), "r"(a[1]), "r"(a[2]), "r"(a[3]),
          "r"(b[0]), "r"(b[1]));
}
__device__ __forceinline__ uint32_t smem_u32(const void* p) {
    return (uint32_t)__cvta_generic_to_shared(p);
}
__device__ __forceinline__ void cp16(uint32_t dst, const void* src, int sz) {
    asm volatile("cp.async.cg.shared.global [%0], [%1], 16, %2;"
                 :: "r"(dst), "l"(src), "r"(sz));
}
__device__ __forceinline__ void cp_commit() {
    asm volatile("cp.async.commit_group;");
}
__device__ __forceinline__ void cp_wait0() {
    asm volatile("cp.async.wait_group 0;");
}

// ---------------- small kernels ----------------
__global__ void zero_kernel() {
    if (threadIdx.x < TOT_E) g_counts[threadIdx.x] = 0;
}

__global__ void router_kernel(const float* __restrict__ x,
                              const float* __restrict__ spike,
                              const float* __restrict__ Wr,
                              const float* __restrict__ br) {
    int warp = (blockIdx.x * blockDim.x + threadIdx.x) >> 5;
    int lane = threadIdx.x & 31;
    if (warp >= BTOK) return;
    const float* xr = x + (size_t)warp * DIN;

    float acc[TOT_E];
#pragma unroll
    for (int e = 0; e < TOT_E; e++) acc[e] = 0.f;
    for (int k = lane; k < DIN; k += 32) {
        float xv = xr[k];
        const float* wrow = Wr + k * TOT_E;
#pragma unroll
        for (int e = 0; e < TOT_E; e++) acc[e] += xv * wrow[e];
    }
#pragma unroll
    for (int e = 0; e < TOT_E; e++)
#pragma unroll
        for (int off = 16; off; off >>= 1)
            acc[e] += __shfl_xor_sync(0xffffffffu, acc[e], off);
    float sp = (lane < TSPK) ? spike[warp * TSPK + lane] : 0.f;
#pragma unroll
    for (int off = 16; off; off >>= 1)
        sp += __shfl_xor_sync(0xffffffffu, sp, off);

    if (lane == 0) {
        float avg = sp * (1.f / TSPK);
        float lg[TOT_E];
#pragma unroll
        for (int e = 0; e < TOT_E; e++)
            lg[e] = acc[e] + br[e] + (e >= SPIKE_E0 ? avg : 0.f);
        float m = lg[0];
#pragma unroll
        for (int e = 1; e < TOT_E; e++) m = fmaxf(m, lg[e]);
        float p[TOT_E]; float Z = 0.f;
#pragma unroll
        for (int e = 0; e < TOT_E; e++) { p[e] = expf(lg[e] - m); Z += p[e]; }
        float invZ = 1.f / Z;
#pragma unroll
        for (int e = 0; e < TOT_E; e++) p[e] *= invZ;
        int e0 = 0;
#pragma unroll
        for (int e = 1; e < TOT_E; e++) if (p[e] > p[e0]) e0 = e;
        int e1 = (e0 == 0) ? 1 : 0;
#pragma unroll
        for (int e = 0; e < TOT_E; e++)
            if (e != e0 && p[e] > p[e1]) e1 = e;
        float s = p[e0] + p[e1] + 1e-9f;
        g_topk_e[2 * warp + 0] = e0;
        g_topk_e[2 * warp + 1] = e1;
        g_topk_w[2 * warp + 0] = p[e0] / s;
        g_topk_w[2 * warp + 1] = p[e1] / s;
        atomicAdd(&g_counts[e0], 1);
        atomicAdd(&g_counts[e1], 1);
    }
}

__global__ void offsets_kernel() {
    int off = 0;
    int offs[TOT_E];
    for (int e = 0; e < TOT_E; e++) {
        offs[e] = off;
        g_cursor[e] = off;
        off += g_counts[e];
    }
    int nt = 0;
    for (int e = 0; e < TOT_E; e++) {
        int n = g_counts[e];
        int r0 = offs[e];
        for (int t = 0; t < n; t += BM) {
            g_tile_e[nt] = e;
            g_tile_r0[nt] = r0 + t;
            int r1 = r0 + t + BM;
            int re = r0 + n;
            g_tile_r1[nt] = r1 < re ? r1 : re;
            nt++;
        }
    }
    g_num_tiles = nt;
}

__global__ void scatter_kernel() {
    __shared__ int cnt[TOT_E];
    __shared__ int base[TOT_E];
    int tid = threadIdx.x;
    if (tid < TOT_E) cnt[tid] = 0;
    __syncthreads();
    int i = blockIdx.x * blockDim.x + tid;
    int e = g_topk_e[i];
    int loc = atomicAdd(&cnt[e], 1);
    __syncthreads();
    if (tid < TOT_E) base[tid] = atomicAdd(&g_cursor[tid], cnt[tid]);
    __syncthreads();
    int pos = base[e] + loc;
    g_perm[pos] = i >> 1;
    g_wgt[pos]  = g_topk_w[i];
    g_rowOf[i]  = pos;
}

// x (fp32) -> g_xh (half)
__global__ void cvtx_kernel(const float4* __restrict__ x) {
    int i = blockIdx.x * blockDim.x + threadIdx.x;
    float4 v = x[i];
    ((__half2*)g_xh)[2 * i]     = __floats2half2_rn(v.x, v.y);
    ((__half2*)g_xh)[2 * i + 1] = __floats2half2_rn(v.z, v.w);
}

// W[e][K][N] fp32 -> Wt[e][N][K] half
template<bool FIRST>
__global__ void transpose_kernel(const float* __restrict__ W, int K, int N) {
    __half* Wt = FIRST ? g_W1t : g_W2t;
    __shared__ float t[32][33];
    int e = blockIdx.z;
    const float* Ws = W + (size_t)e * K * N;
    __half* Wd = Wt + (size_t)e * K * N;
    int k0 = blockIdx.x * 32, n0 = blockIdx.y * 32;
    int tx = threadIdx.x, ty = threadIdx.y;   // 32 x 8
#pragma unroll
    for (int i = 0; i < 32; i += 8)
        t[ty + i][tx] = Ws[(size_t)(k0 + ty + i) * N + n0 + tx];
    __syncthreads();
#pragma unroll
    for (int i = 0; i < 32; i += 8)
        Wd[(size_t)(n0 + ty + i) * K + k0 + tx] = __float2half_rn(t[tx][ty + i]);
}

// ---------------- fp16 grouped GEMM, cp.async double-buffered --------------
// BM=128 BN=128 BKH=32, 8 warps (2x4), warp tile 64x32, mma.m16n8k16
template<bool FIRST>
__global__ __launch_bounds__(256, 2)
void gemm_kernel(const float* __restrict__ bias) {
    const int KDIM = FIRST ? DIN : DHID;
    const int NDIM = FIRST ? DHID : DOUT;
    const __half* A0 = FIRST ? g_xh : g_h;
    const __half* Bt = FIRST ? g_W1t : g_W2t;

    __shared__ __half As[2][BM][SROW];
    __shared__ __half Bs[2][BN][SROW];

    int bt = blockIdx.x;
    if (bt >= g_num_tiles) return;
    int e  = g_tile_e[bt];
    int r0 = g_tile_r0[bt];
    int r1 = g_tile_r1[bt];
    int n0 = blockIdx.y * BN;

    const __half* Bexp = Bt + (size_t)e * NDIM * KDIM;

    int tid  = threadIdx.x;
    int lane = tid & 31;
    int wid  = tid >> 5;
    int gidl = lane >> 2;
    int tg   = lane & 3;
    int wm   = (wid >> 2) * 64;
    int wn   = (wid & 3) * 32;

    // staging: 2 threads per row, each 16 halves (two 16B cp.async)
    int srow = tid >> 1;
    int scol = (tid & 1) * 16;
    int ra = r0 + srow;
    bool av = ra < r1;
    const __half* aRow;
    if (FIRST) aRow = A0 + (av ? (size_t)g_perm[ra] * KDIM : 0) + scol;
    else       aRow = A0 + (av ? (size_t)ra * KDIM : 0) + scol;
    const __half* bRow = Bexp + (size_t)(n0 + srow) * KDIM + scol;
    int asz = av ? 16 : 0;
    uint32_t aDst0 = smem_u32(&As[0][srow][scol]);
    uint32_t bDst0 = smem_u32(&Bs[0][srow][scol]);
    const uint32_t A_STAGE_B = (uint32_t)(BM * SROW * 2);   // bytes per A stage
    const uint32_t B_STAGE_B = (uint32_t)(BN * SROW * 2);

    float acc[4][4][4];
#pragma unroll
    for (int a = 0; a < 4; a++)
#pragma unroll
        for (int b = 0; b < 4; b++)
#pragma unroll
            for (int c = 0; c < 4; c++) acc[a][b][c] = 0.f;

    const int NC = KDIM / BKH;

    // ---- prologue: stage slab 0 ----
    {
        cp16(aDst0,      aRow,     asz);
        cp16(aDst0 + 16, aRow + 8, asz);
        cp16(bDst0,      bRow,     16);
        cp16(bDst0 + 16, bRow + 8, 16);
        cp_commit();
    }

    for (int c = 0; c < NC; c++) {
        cp_wait0();
        __syncthreads();
        int cur = c & 1;

        // prefetch slab c+1
        if (c + 1 < NC) {
            int nxt = (c + 1) & 1;
            const __half* as = aRow + (c + 1) * BKH;
            const __half* bs = bRow + (c + 1) * BKH;
            uint32_t ad = aDst0 + nxt * A_STAGE_B;
            uint32_t bd = bDst0 + nxt * B_STAGE_B;
            cp16(ad,      as,     asz);
            cp16(ad + 16, as + 8, asz);
            cp16(bd,      bs,     16);
            cp16(bd + 16, bs + 8, 16);
            cp_commit();
        }

        // ---- compute slab c: two k16 steps ----
#pragma unroll
        for (int kk = 0; kk < BKH; kk += 16) {
            uint32_t af[4][4], bf[4][2];
#pragma unroll
            for (int mi = 0; mi < 4; mi++) {
                int m = wm + mi * 16;
                af[mi][0] = *(const uint32_t*)&As[cur][m + gidl    ][kk + 2 * tg    ];
                af[mi][1] = *(const uint32_t*)&As[cur][m + gidl + 8][kk + 2 * tg    ];
                af[mi][2] = *(const uint32_t*)&As[cur][m + gidl    ][kk + 2 * tg + 8];
                af[mi][3] = *(const uint32_t*)&As[cur][m + gidl + 8][kk + 2 * tg + 8];
            }
#pragma unroll
            for (int ni = 0; ni < 4; ni++) {
                int n = wn + ni * 8 + gidl;
                bf[ni][0] = *(const uint32_t*)&Bs[cur][n][kk + 2 * tg    ];
                bf[ni][1] = *(const uint32_t*)&Bs[cur][n][kk + 2 * tg + 8];
            }
#pragma unroll
            for (int mi = 0; mi < 4; mi++)
#pragma unroll
                for (int ni = 0; ni < 4; ni++)
                    mma_f16(acc[mi][ni], af[mi], bf[ni]);
        }
        __syncthreads();
    }

    // ---- epilogue ----
    const float* be = bias + (size_t)e * NDIM;
#pragma unroll
    for (int mi = 0; mi < 4; mi++) {
#pragma unroll
        for (int ri = 0; ri < 2; ri++) {
            int r = r0 + wm + mi * 16 + gidl + ri * 8;
            if (r >= r1) continue;
            float sc = FIRST ? 1.f : g_wgt[r];
#pragma unroll
            for (int ni = 0; ni < 4; ni++) {
                int cc = n0 + wn + ni * 8 + 2 * tg;
                float v0 = acc[mi][ni][ri * 2 + 0] + be[cc];
                float v1 = acc[mi][ni][ri * 2 + 1] + be[cc + 1];
                if (FIRST) {
                    v0 = fmaxf(v0, 0.f);
                    v1 = fmaxf(v1, 0.f);
                    *reinterpret_cast<__half2*>(g_h + (size_t)r * NDIM + cc) =
                        __floats2half2_rn(v0, v1);
                } else {
                    v0 *= sc; v1 *= sc;
                    *reinterpret_cast<float2*>(g_z + (size_t)r * NDIM + cc) =
                        make_float2(v0, v1);
                }
            }
        }
    }
}

// ---------------- combine ----------------
__global__ void combine_kernel(float4* __restrict__ out) {
    int i = blockIdx.x * blockDim.x + threadIdx.x;
    const int C4 = DOUT / 4;
    int t = i / C4;
    int c = i % C4;
    int ra = g_rowOf[2 * t + 0];
    int rb = g_rowOf[2 * t + 1];
    const float4* z4 = (const float4*)g_z;
    float4 a = z4[(size_t)ra * C4 + c];
    float4 b = z4[(size_t)rb * C4 + c];
    out[i] = make_float4(a.x + b.x, a.y + b.y, a.z + b.z, a.w + b.w);
}

// ---------------- launch ----------------
extern "C" void kernel_launch(void* const* d_in, const int* in_sizes, int n_in,
                              void* d_out, int out_size) {
    const float* x     = (const float*)d_in[0];
    const float* spike = (const float*)d_in[1];
    const float* Wr    = (const float*)d_in[2];
    const float* br    = (const float*)d_in[3];
    const float* W1    = (const float*)d_in[4];
    const float* b1    = (const float*)d_in[5];
    const float* W2    = (const float*)d_in[6];
    const float* b2    = (const float*)d_in[7];
    float* out = (float*)d_out;

    zero_kernel<<<1, 32>>>();
    router_kernel<<<BTOK / 8, 256>>>(x, spike, Wr, br);
    offsets_kernel<<<1, 1>>>();
    scatter_kernel<<<NPAIRS / 256, 256>>>();
    cvtx_kernel<<<(BTOK * DIN / 4) / 256, 256>>>((const float4*)x);
    transpose_kernel<true><<<dim3(DIN / 32, DHID / 32, TOT_E), dim3(32, 8)>>>(W1, DIN, DHID);
    transpose_kernel<false><<<dim3(DHID / 32, DOUT / 32, TOT_E), dim3(32, 8)>>>(W2, DHID, DOUT);

    gemm_kernel<true><<<dim3(MAX_TILES, DHID / BN), 256>>>(b1);
    gemm_kernel<false><<<dim3(MAX_TILES, DOUT / BN), 256>>>(b2);

    combine_kernel<<<(BTOK * DOUT / 4) / 256, 256>>>((float4*)out);
}

// round 8
// speedup vs baseline: 2.0908x; 1.1395x over previous
#include <cuda_runtime.h>
#include <cuda_fp16.h>
#include <stdint.h>

// ---------------- problem constants ----------------
#define TOT_E      10
#define SPIKE_E0   8
#define DIN        512
#define DHID       1024
#define DOUT       256
#define BTOK       32768
#define TSPK       16
#define NPAIRS     (BTOK * 2)
#define BM 128
#define BN 128
#define BKH 32                             // K halves per slab
#define MAX_TILES  (NPAIRS / BM + TOT_E)   // 522
#define SROW 40                            // smem row stride in halves (80 B)
#define SROWB (SROW * 2)                   // 80 bytes

// ---------------- device scratch (device-code references only) ------------
__device__ __half g_h[(size_t)NPAIRS * DHID];
__device__ float  g_z[(size_t)NPAIRS * DOUT];
__device__ __half g_xh[(size_t)BTOK * DIN];
__device__ __half g_W1t[(size_t)TOT_E * DIN * DHID];   // [E][N=DHID][K=DIN]
__device__ __half g_W2t[(size_t)TOT_E * DHID * DOUT];  // [E][N=DOUT][K=DHID]
__device__ int    g_perm[NPAIRS];
__device__ float  g_wgt[NPAIRS];
__device__ int    g_rowOf[NPAIRS];
__device__ int    g_topk_e[NPAIRS];
__device__ float  g_topk_w[NPAIRS];
__device__ int    g_counts[TOT_E];
__device__ int    g_cursor[TOT_E];
__device__ int    g_tile_e[MAX_TILES];
__device__ int    g_tile_r0[MAX_TILES];
__device__ int    g_tile_r1[MAX_TILES];
__device__ int    g_num_tiles;

// ---------------- helpers ----------------
__device__ __forceinline__ void mma_f16(float* c, const uint32_t* a, const uint32_t* b) {
    asm volatile(
        "mma.sync.aligned.m16n8k16.row.col.f32.f16.f16.f32 "
        "{%0,%1,%2,%3}, {%4,%5,%6,%7}, {%8,%9}, {%0,%1,%2,%3};"
        : "+f"(c[0]), "+f"(c[1]), "+f"(c[2]), "+f"(c[3])
        : "r"(a[0]), "r"(a[1]), "r"(a[2]), "r"(a[3]),
          "r"(b[0]), "r"(b[1]));
}
__device__ __forceinline__ void ldsm_x4(uint32_t& r0, uint32_t& r1, uint32_t& r2,
                                        uint32_t& r3, uint32_t addr) {
    asm volatile("ldmatrix.sync.aligned.m8n8.x4.shared.b16 {%0,%1,%2,%3}, [%4];"
                 : "=r"(r0), "=r"(r1), "=r"(r2), "=r"(r3) : "r"(addr));
}
__device__ __forceinline__ uint32_t smem_u32(const void* p) {
    return (uint32_t)__cvta_generic_to_shared(p);
}
__device__ __forceinline__ void cp16(uint32_t dst, const void* src, int sz) {
    asm volatile("cp.async.cg.shared.global [%0], [%1], 16, %2;"
                 :: "r"(dst), "l"(src), "r"(sz));
}
__device__ __forceinline__ void cp_commit() {
    asm volatile("cp.async.commit_group;");
}
__device__ __forceinline__ void cp_wait0() {
    asm volatile("cp.async.wait_group 0;");
}

// ---------------- small kernels ----------------
__global__ void zero_kernel() {
    if (threadIdx.x < TOT_E) g_counts[threadIdx.x] = 0;
}

__global__ void router_kernel(const float* __restrict__ x,
                              const float* __restrict__ spike,
                              const float* __restrict__ Wr,
                              const float* __restrict__ br) {
    int warp = (blockIdx.x * blockDim.x + threadIdx.x) >> 5;
    int lane = threadIdx.x & 31;
    if (warp >= BTOK) return;
    const float* xr = x + (size_t)warp * DIN;

    float acc[TOT_E];
#pragma unroll
    for (int e = 0; e < TOT_E; e++) acc[e] = 0.f;
    for (int k = lane; k < DIN; k += 32) {
        float xv = xr[k];
        const float* wrow = Wr + k * TOT_E;
#pragma unroll
        for (int e = 0; e < TOT_E; e++) acc[e] += xv * wrow[e];
    }
#pragma unroll
    for (int e = 0; e < TOT_E; e++)
#pragma unroll
        for (int off = 16; off; off >>= 1)
            acc[e] += __shfl_xor_sync(0xffffffffu, acc[e], off);
    float sp = (lane < TSPK) ? spike[warp * TSPK + lane] : 0.f;
#pragma unroll
    for (int off = 16; off; off >>= 1)
        sp += __shfl_xor_sync(0xffffffffu, sp, off);

    if (lane == 0) {
        float avg = sp * (1.f / TSPK);
        float lg[TOT_E];
#pragma unroll
        for (int e = 0; e < TOT_E; e++)
            lg[e] = acc[e] + br[e] + (e >= SPIKE_E0 ? avg : 0.f);
        float m = lg[0];
#pragma unroll
        for (int e = 1; e < TOT_E; e++) m = fmaxf(m, lg[e]);
        float p[TOT_E]; float Z = 0.f;
#pragma unroll
        for (int e = 0; e < TOT_E; e++) { p[e] = expf(lg[e] - m); Z += p[e]; }
        float invZ = 1.f / Z;
#pragma unroll
        for (int e = 0; e < TOT_E; e++) p[e] *= invZ;
        int e0 = 0;
#pragma unroll
        for (int e = 1; e < TOT_E; e++) if (p[e] > p[e0]) e0 = e;
        int e1 = (e0 == 0) ? 1 : 0;
#pragma unroll
        for (int e = 0; e < TOT_E; e++)
            if (e != e0 && p[e] > p[e1]) e1 = e;
        float s = p[e0] + p[e1] + 1e-9f;
        g_topk_e[2 * warp + 0] = e0;
        g_topk_e[2 * warp + 1] = e1;
        g_topk_w[2 * warp + 0] = p[e0] / s;
        g_topk_w[2 * warp + 1] = p[e1] / s;
        atomicAdd(&g_counts[e0], 1);
        atomicAdd(&g_counts[e1], 1);
    }
}

__global__ void offsets_kernel() {
    int off = 0;
    int offs[TOT_E];
    for (int e = 0; e < TOT_E; e++) {
        offs[e] = off;
        g_cursor[e] = off;
        off += g_counts[e];
    }
    int nt = 0;
    for (int e = 0; e < TOT_E; e++) {
        int n = g_counts[e];
        int r0 = offs[e];
        for (int t = 0; t < n; t += BM) {
            g_tile_e[nt] = e;
            g_tile_r0[nt] = r0 + t;
            int r1 = r0 + t + BM;
            int re = r0 + n;
            g_tile_r1[nt] = r1 < re ? r1 : re;
            nt++;
        }
    }
    g_num_tiles = nt;
}

__global__ void scatter_kernel() {
    __shared__ int cnt[TOT_E];
    __shared__ int base[TOT_E];
    int tid = threadIdx.x;
    if (tid < TOT_E) cnt[tid] = 0;
    __syncthreads();
    int i = blockIdx.x * blockDim.x + tid;
    int e = g_topk_e[i];
    int loc = atomicAdd(&cnt[e], 1);
    __syncthreads();
    if (tid < TOT_E) base[tid] = atomicAdd(&g_cursor[tid], cnt[tid]);
    __syncthreads();
    int pos = base[e] + loc;
    g_perm[pos] = i >> 1;
    g_wgt[pos]  = g_topk_w[i];
    g_rowOf[i]  = pos;
}

// x (fp32) -> g_xh (half)
__global__ void cvtx_kernel(const float4* __restrict__ x) {
    int i = blockIdx.x * blockDim.x + threadIdx.x;
    float4 v = x[i];
    ((__half2*)g_xh)[2 * i]     = __floats2half2_rn(v.x, v.y);
    ((__half2*)g_xh)[2 * i + 1] = __floats2half2_rn(v.z, v.w);
}

// W[e][K][N] fp32 -> Wt[e][N][K] half
template<bool FIRST>
__global__ void transpose_kernel(const float* __restrict__ W, int K, int N) {
    __half* Wt = FIRST ? g_W1t : g_W2t;
    __shared__ float t[32][33];
    int e = blockIdx.z;
    const float* Ws = W + (size_t)e * K * N;
    __half* Wd = Wt + (size_t)e * K * N;
    int k0 = blockIdx.x * 32, n0 = blockIdx.y * 32;
    int tx = threadIdx.x, ty = threadIdx.y;   // 32 x 8
#pragma unroll
    for (int i = 0; i < 32; i += 8)
        t[ty + i][tx] = Ws[(size_t)(k0 + ty + i) * N + n0 + tx];
    __syncthreads();
#pragma unroll
    for (int i = 0; i < 32; i += 8)
        Wd[(size_t)(n0 + ty + i) * K + k0 + tx] = __float2half_rn(t[tx][ty + i]);
}

// ---------------- fp16 grouped GEMM: cp.async + ldmatrix -------------------
// BM=128 BN=128 BKH=32, 8 warps (2x4), warp tile 64x32, mma.m16n8k16
template<bool FIRST>
__global__ __launch_bounds__(256, 2)
void gemm_kernel(const float* __restrict__ bias) {
    const int KDIM = FIRST ? DIN : DHID;
    const int NDIM = FIRST ? DHID : DOUT;
    const __half* A0 = FIRST ? g_xh : g_h;
    const __half* Bt = FIRST ? g_W1t : g_W2t;

    __shared__ __half As[2][BM][SROW];
    __shared__ __half Bs[2][BN][SROW];

    int bt = blockIdx.x;
    if (bt >= g_num_tiles) return;
    int e  = g_tile_e[bt];
    int r0 = g_tile_r0[bt];
    int r1 = g_tile_r1[bt];
    int n0 = blockIdx.y * BN;

    const __half* Bexp = Bt + (size_t)e * NDIM * KDIM;

    int tid  = threadIdx.x;
    int lane = tid & 31;
    int wid  = tid >> 5;
    int gidl = lane >> 2;
    int tg   = lane & 3;
    int wm   = (wid >> 2) * 64;
    int wn   = (wid & 3) * 32;

    // staging: 2 threads per row, each 16 halves (two 16B cp.async)
    int srow = tid >> 1;
    int scol = (tid & 1) * 16;
    int ra = r0 + srow;
    bool av = ra < r1;
    const __half* aRow;
    if (FIRST) aRow = A0 + (av ? (size_t)g_perm[ra] * KDIM : 0) + scol;
    else       aRow = A0 + (av ? (size_t)ra * KDIM : 0) + scol;
    const __half* bRow = Bexp + (size_t)(n0 + srow) * KDIM + scol;
    int asz = av ? 16 : 0;
    uint32_t aDst0 = smem_u32(&As[0][srow][scol]);
    uint32_t bDst0 = smem_u32(&Bs[0][srow][scol]);
    const uint32_t A_STAGE_B = (uint32_t)(BM * SROWB);
    const uint32_t B_STAGE_B = (uint32_t)(BN * SROWB);

    // ldmatrix lane-address bases
    // A x4: lanes 0-15 -> rows wm+(lane&15), k byte-offset 0; lanes 16-31 same rows, +16B
    uint32_t aLdBase = smem_u32(&As[0][0][0])
                     + (uint32_t)(wm + (lane & 15)) * SROWB
                     + (uint32_t)(lane >> 4) * 16;
    // B x4: matrix0: rows wn+(lane&7), k+0 | matrix1: same rows, +16B
    //       matrix2: rows wn+8+(lane&7), k+0 | matrix3: rows+8, +16B
    uint32_t bLdBase = smem_u32(&Bs[0][0][0])
                     + (uint32_t)(wn + (lane & 7) + ((lane >> 4) & 1) * 8) * SROWB
                     + (uint32_t)((lane >> 3) & 1) * 16;

    float acc[4][4][4];
#pragma unroll
    for (int a = 0; a < 4; a++)
#pragma unroll
        for (int b = 0; b < 4; b++)
#pragma unroll
            for (int c = 0; c < 4; c++) acc[a][b][c] = 0.f;

    const int NC = KDIM / BKH;

    // ---- prologue: stage slab 0 ----
    {
        cp16(aDst0,      aRow,     asz);
        cp16(aDst0 + 16, aRow + 8, asz);
        cp16(bDst0,      bRow,     16);
        cp16(bDst0 + 16, bRow + 8, 16);
        cp_commit();
    }

    for (int c = 0; c < NC; c++) {
        cp_wait0();
        __syncthreads();
        int cur = c & 1;
        uint32_t aB = aLdBase + (uint32_t)cur * A_STAGE_B;
        uint32_t bB = bLdBase + (uint32_t)cur * B_STAGE_B;

        // prefetch slab c+1
        if (c + 1 < NC) {
            int nxt = (c + 1) & 1;
            const __half* as = aRow + (c + 1) * BKH;
            const __half* bs = bRow + (c + 1) * BKH;
            uint32_t ad = aDst0 + nxt * A_STAGE_B;
            uint32_t bd = bDst0 + nxt * B_STAGE_B;
            cp16(ad,      as,     asz);
            cp16(ad + 16, as + 8, asz);
            cp16(bd,      bs,     16);
            cp16(bd + 16, bs + 8, 16);
            cp_commit();
        }

        // ---- compute slab c: two k16 steps ----
#pragma unroll
        for (int kk = 0; kk < 2; kk++) {
            uint32_t kB = (uint32_t)kk * 32;    // 16 halves = 32 bytes
            uint32_t af[4][4], bf4[2][4];
#pragma unroll
            for (int mi = 0; mi < 4; mi++)
                ldsm_x4(af[mi][0], af[mi][1], af[mi][2], af[mi][3],
                        aB + kB + (uint32_t)mi * (16 * SROWB));
#pragma unroll
            for (int nj = 0; nj < 2; nj++)
                ldsm_x4(bf4[nj][0], bf4[nj][1], bf4[nj][2], bf4[nj][3],
                        bB + kB + (uint32_t)nj * (16 * SROWB));
#pragma unroll
            for (int mi = 0; mi < 4; mi++)
#pragma unroll
                for (int ni = 0; ni < 4; ni++)
                    mma_f16(acc[mi][ni], af[mi], &bf4[ni >> 1][(ni & 1) * 2]);
        }
        __syncthreads();
    }

    // ---- epilogue ----
    const float* be = bias + (size_t)e * NDIM;
#pragma unroll
    for (int mi = 0; mi < 4; mi++) {
#pragma unroll
        for (int ri = 0; ri < 2; ri++) {
            int r = r0 + wm + mi * 16 + gidl + ri * 8;
            if (r >= r1) continue;
            float sc = FIRST ? 1.f : g_wgt[r];
#pragma unroll
            for (int ni = 0; ni < 4; ni++) {
                int cc = n0 + wn + ni * 8 + 2 * tg;
                float v0 = acc[mi][ni][ri * 2 + 0] + be[cc];
                float v1 = acc[mi][ni][ri * 2 + 1] + be[cc + 1];
                if (FIRST) {
                    v0 = fmaxf(v0, 0.f);
                    v1 = fmaxf(v1, 0.f);
                    *reinterpret_cast<__half2*>(g_h + (size_t)r * NDIM + cc) =
                        __floats2half2_rn(v0, v1);
                } else {
                    v0 *= sc; v1 *= sc;
                    *reinterpret_cast<float2*>(g_z + (size_t)r * NDIM + cc) =
                        make_float2(v0, v1);
                }
            }
        }
    }
}

// ---------------- combine ----------------
__global__ void combine_kernel(float4* __restrict__ out) {
    int i = blockIdx.x * blockDim.x + threadIdx.x;
    const int C4 = DOUT / 4;
    int t = i / C4;
    int c = i % C4;
    int ra = g_rowOf[2 * t + 0];
    int rb = g_rowOf[2 * t + 1];
    const float4* z4 = (const float4*)g_z;
    float4 a = z4[(size_t)ra * C4 + c];
    float4 b = z4[(size_t)rb * C4 + c];
    out[i] = make_float4(a.x + b.x, a.y + b.y, a.z + b.z, a.w + b.w);
}

// ---------------- launch ----------------
extern "C" void kernel_launch(void* const* d_in, const int* in_sizes, int n_in,
                              void* d_out, int out_size) {
    const float* x     = (const float*)d_in[0];
    const float* spike = (const float*)d_in[1];
    const float* Wr    = (const float*)d_in[2];
    const float* br    = (const float*)d_in[3];
    const float* W1    = (const float*)d_in[4];
    const float* b1    = (const float*)d_in[5];
    const float* W2    = (const float*)d_in[6];
    const float* b2    = (const float*)d_in[7];
    float* out = (float*)d_out;

    zero_kernel<<<1, 32>>>();
    router_kernel<<<BTOK / 8, 256>>>(x, spike, Wr, br);
    offsets_kernel<<<1, 1>>>();
    scatter_kernel<<<NPAIRS / 256, 256>>>();
    cvtx_kernel<<<(BTOK * DIN / 4) / 256, 256>>>((const float4*)x);
    transpose_kernel<true><<<dim3(DIN / 32, DHID / 32, TOT_E), dim3(32, 8)>>>(W1, DIN, DHID);
    transpose_kernel<false><<<dim3(DHID / 32, DOUT / 32, TOT_E), dim3(32, 8)>>>(W2, DHID, DOUT);

    gemm_kernel<true><<<dim3(MAX_TILES, DHID / BN), 256>>>(b1);
    gemm_kernel<false><<<dim3(MAX_TILES, DOUT / BN), 256>>>(b2);

    combine_kernel<<<(BTOK * DOUT / 4) / 256, 256>>>((float4*)out);
}

// round 9
// speedup vs baseline: 2.1164x; 1.0122x over previous
#include <cuda_runtime.h>
#include <cuda_fp16.h>
#include <stdint.h>

// ---------------- problem constants ----------------
#define TOT_E      10
#define SPIKE_E0   8
#define DIN        512
#define DHID       1024
#define DOUT       256
#define BTOK       32768
#define TSPK       16
#define NPAIRS     (BTOK * 2)
#define BM 128
#define BN 128
#define BKH 32                             // K halves per slab
#define MAX_TILES  (NPAIRS / BM + TOT_E)   // 522
#define SROW 40                            // smem row stride in halves (80 B)
#define SROWB (SROW * 2)                   // 80 bytes
#define NSTAGE 3
#define STAGE_HALVES ((BM + BN) * SROW)    // 10240 halves
#define STAGE_B (STAGE_HALVES * 2)         // 20480 bytes
#define DYN_SMEM (NSTAGE * STAGE_B)        // 61440 bytes

// ---------------- device scratch (device-code references only) ------------
__device__ __half g_h[(size_t)NPAIRS * DHID];
__device__ float  g_z[(size_t)NPAIRS * DOUT];
__device__ __half g_xh[(size_t)BTOK * DIN];
__device__ __half g_W1t[(size_t)TOT_E * DIN * DHID];   // [E][N=DHID][K=DIN]
__device__ __half g_W2t[(size_t)TOT_E * DHID * DOUT];  // [E][N=DOUT][K=DHID]
__device__ int    g_perm[NPAIRS];
__device__ float  g_wgt[NPAIRS];
__device__ int    g_rowOf[NPAIRS];
__device__ int    g_topk_e[NPAIRS];
__device__ float  g_topk_w[NPAIRS];
__device__ int    g_counts[TOT_E];
__device__ int    g_cursor[TOT_E];
__device__ int    g_tile_e[MAX_TILES];
__device__ int    g_tile_r0[MAX_TILES];
__device__ int    g_tile_r1[MAX_TILES];
__device__ int    g_num_tiles;

// ---------------- helpers ----------------
__device__ __forceinline__ void mma_f16(float* c, const uint32_t* a, const uint32_t* b) {
    asm volatile(
        "mma.sync.aligned.m16n8k16.row.col.f32.f16.f16.f32 "
        "{%0,%1,%2,%3}, {%4,%5,%6,%7}, {%8,%9}, {%0,%1,%2,%3};"
        : "+f"(c[0]), "+f"(c[1]), "+f"(c[2]), "+f"(c[3])
        : "r"(a[0]), "r"(a[1]), "r"(a[2]), "r"(a[3]),
          "r"(b[0]), "r"(b[1]));
}
__device__ __forceinline__ void ldsm_x4(uint32_t& r0, uint32_t& r1, uint32_t& r2,
                                        uint32_t& r3, uint32_t addr) {
    asm volatile("ldmatrix.sync.aligned.m8n8.x4.shared.b16 {%0,%1,%2,%3}, [%4];"
                 : "=r"(r0), "=r"(r1), "=r"(r2), "=r"(r3) : "r"(addr));
}
__device__ __forceinline__ uint32_t smem_u32(const void* p) {
    return (uint32_t)__cvta_generic_to_shared(p);
}
__device__ __forceinline__ void cp16(uint32_t dst, const void* src, int sz) {
    asm volatile("cp.async.cg.shared.global [%0], [%1], 16, %2;"
                 :: "r"(dst), "l"(src), "r"(sz));
}
__device__ __forceinline__ void cp_commit() {
    asm volatile("cp.async.commit_group;");
}
template<int N>
__device__ __forceinline__ void cp_wait() {
    asm volatile("cp.async.wait_group %0;" :: "n"(N));
}

// ---------------- small kernels ----------------
__global__ void zero_kernel() {
    if (threadIdx.x < TOT_E) g_counts[threadIdx.x] = 0;
}

__global__ void router_kernel(const float* __restrict__ x,
                              const float* __restrict__ spike,
                              const float* __restrict__ Wr,
                              const float* __restrict__ br) {
    int warp = (blockIdx.x * blockDim.x + threadIdx.x) >> 5;
    int lane = threadIdx.x & 31;
    if (warp >= BTOK) return;
    const float* xr = x + (size_t)warp * DIN;

    float acc[TOT_E];
#pragma unroll
    for (int e = 0; e < TOT_E; e++) acc[e] = 0.f;
    for (int k = lane; k < DIN; k += 32) {
        float xv = xr[k];
        const float* wrow = Wr + k * TOT_E;
#pragma unroll
        for (int e = 0; e < TOT_E; e++) acc[e] += xv * wrow[e];
    }
#pragma unroll
    for (int e = 0; e < TOT_E; e++)
#pragma unroll
        for (int off = 16; off; off >>= 1)
            acc[e] += __shfl_xor_sync(0xffffffffu, acc[e], off);
    float sp = (lane < TSPK) ? spike[warp * TSPK + lane] : 0.f;
#pragma unroll
    for (int off = 16; off; off >>= 1)
        sp += __shfl_xor_sync(0xffffffffu, sp, off);

    if (lane == 0) {
        float avg = sp * (1.f / TSPK);
        float lg[TOT_E];
#pragma unroll
        for (int e = 0; e < TOT_E; e++)
            lg[e] = acc[e] + br[e] + (e >= SPIKE_E0 ? avg : 0.f);
        float m = lg[0];
#pragma unroll
        for (int e = 1; e < TOT_E; e++) m = fmaxf(m, lg[e]);
        float p[TOT_E]; float Z = 0.f;
#pragma unroll
        for (int e = 0; e < TOT_E; e++) { p[e] = expf(lg[e] - m); Z += p[e]; }
        float invZ = 1.f / Z;
#pragma unroll
        for (int e = 0; e < TOT_E; e++) p[e] *= invZ;
        int e0 = 0;
#pragma unroll
        for (int e = 1; e < TOT_E; e++) if (p[e] > p[e0]) e0 = e;
        int e1 = (e0 == 0) ? 1 : 0;
#pragma unroll
        for (int e = 0; e < TOT_E; e++)
            if (e != e0 && p[e] > p[e1]) e1 = e;
        float s = p[e0] + p[e1] + 1e-9f;
        g_topk_e[2 * warp + 0] = e0;
        g_topk_e[2 * warp + 1] = e1;
        g_topk_w[2 * warp + 0] = p[e0] / s;
        g_topk_w[2 * warp + 1] = p[e1] / s;
        atomicAdd(&g_counts[e0], 1);
        atomicAdd(&g_counts[e1], 1);
    }
}

__global__ void offsets_kernel() {
    int off = 0;
    int offs[TOT_E];
    for (int e = 0; e < TOT_E; e++) {
        offs[e] = off;
        g_cursor[e] = off;
        off += g_counts[e];
    }
    int nt = 0;
    for (int e = 0; e < TOT_E; e++) {
        int n = g_counts[e];
        int r0 = offs[e];
        for (int t = 0; t < n; t += BM) {
            g_tile_e[nt] = e;
            g_tile_r0[nt] = r0 + t;
            int r1 = r0 + t + BM;
            int re = r0 + n;
            g_tile_r1[nt] = r1 < re ? r1 : re;
            nt++;
        }
    }
    g_num_tiles = nt;
}

__global__ void scatter_kernel() {
    __shared__ int cnt[TOT_E];
    __shared__ int base[TOT_E];
    int tid = threadIdx.x;
    if (tid < TOT_E) cnt[tid] = 0;
    __syncthreads();
    int i = blockIdx.x * blockDim.x + tid;
    int e = g_topk_e[i];
    int loc = atomicAdd(&cnt[e], 1);
    __syncthreads();
    if (tid < TOT_E) base[tid] = atomicAdd(&g_cursor[tid], cnt[tid]);
    __syncthreads();
    int pos = base[e] + loc;
    g_perm[pos] = i >> 1;
    g_wgt[pos]  = g_topk_w[i];
    g_rowOf[i]  = pos;
}

// x (fp32) -> g_xh (half)
__global__ void cvtx_kernel(const float4* __restrict__ x) {
    int i = blockIdx.x * blockDim.x + threadIdx.x;
    float4 v = x[i];
    ((__half2*)g_xh)[2 * i]     = __floats2half2_rn(v.x, v.y);
    ((__half2*)g_xh)[2 * i + 1] = __floats2half2_rn(v.z, v.w);
}

// W[e][K][N] fp32 -> Wt[e][N][K] half
template<bool FIRST>
__global__ void transpose_kernel(const float* __restrict__ W, int K, int N) {
    __half* Wt = FIRST ? g_W1t : g_W2t;
    __shared__ float t[32][33];
    int e = blockIdx.z;
    const float* Ws = W + (size_t)e * K * N;
    __half* Wd = Wt + (size_t)e * K * N;
    int k0 = blockIdx.x * 32, n0 = blockIdx.y * 32;
    int tx = threadIdx.x, ty = threadIdx.y;   // 32 x 8
#pragma unroll
    for (int i = 0; i < 32; i += 8)
        t[ty + i][tx] = Ws[(size_t)(k0 + ty + i) * N + n0 + tx];
    __syncthreads();
#pragma unroll
    for (int i = 0; i < 32; i += 8)
        Wd[(size_t)(n0 + ty + i) * K + k0 + tx] = __float2half_rn(t[tx][ty + i]);
}

// ---------------- fp16 grouped GEMM: 3-stage cp.async, 1 barrier/slab ------
// BM=128 BN=128 BKH=32, 8 warps (2x4), warp tile 64x32, mma.m16n8k16
template<bool FIRST>
__global__ __launch_bounds__(256, 2)
void gemm_kernel(const float* __restrict__ bias) {
    const int KDIM = FIRST ? DIN : DHID;
    const int NDIM = FIRST ? DHID : DOUT;
    const __half* A0 = FIRST ? g_xh : g_h;
    const __half* Bt = FIRST ? g_W1t : g_W2t;

    extern __shared__ __half smem[];   // NSTAGE stages of [A(128x40) | B(128x40)]

    int bt = blockIdx.x;
    if (bt >= g_num_tiles) return;
    int e  = g_tile_e[bt];
    int r0 = g_tile_r0[bt];
    int r1 = g_tile_r1[bt];
    int n0 = blockIdx.y * BN;

    const __half* Bexp = Bt + (size_t)e * NDIM * KDIM;

    int tid  = threadIdx.x;
    int lane = tid & 31;
    int wid  = tid >> 5;
    int gidl = lane >> 2;
    int tg   = lane & 3;
    int wm   = (wid >> 2) * 64;
    int wn   = (wid & 3) * 32;

    // staging: 2 threads per row, each 16 halves (two 16B cp.async)
    int srow = tid >> 1;
    int scol = (tid & 1) * 16;
    int ra = r0 + srow;
    bool av = ra < r1;
    const __half* aRow;
    if (FIRST) aRow = A0 + (av ? (size_t)g_perm[ra] * KDIM : 0) + scol;
    else       aRow = A0 + (av ? (size_t)ra * KDIM : 0) + scol;
    const __half* bRow = Bexp + (size_t)(n0 + srow) * KDIM + scol;
    int asz = av ? 16 : 0;
    uint32_t sBase = smem_u32(smem);
    uint32_t aDst0 = sBase + (uint32_t)(srow * SROWB + scol * 2);
    uint32_t bDst0 = aDst0 + (uint32_t)(BM * SROWB);

    // ldmatrix lane-address bases (within stage 0)
    uint32_t aLdBase = sBase
                     + (uint32_t)(wm + (lane & 15)) * SROWB
                     + (uint32_t)(lane >> 4) * 16;
    uint32_t bLdBase = sBase + (uint32_t)(BM * SROWB)
                     + (uint32_t)(wn + (lane & 7) + ((lane >> 4) & 1) * 8) * SROWB
                     + (uint32_t)((lane >> 3) & 1) * 16;

    float acc[4][4][4];
#pragma unroll
    for (int a = 0; a < 4; a++)
#pragma unroll
        for (int b = 0; b < 4; b++)
#pragma unroll
            for (int c = 0; c < 4; c++) acc[a][b][c] = 0.f;

    const int NC = KDIM / BKH;

    // ---- prologue: stage slabs 0 and 1 ----
#pragma unroll
    for (int c = 0; c < 2; c++) {
        uint32_t off = (uint32_t)c * STAGE_B;
        const __half* as = aRow + c * BKH;
        const __half* bs = bRow + c * BKH;
        cp16(aDst0 + off,      as,     asz);
        cp16(aDst0 + off + 16, as + 8, asz);
        cp16(bDst0 + off,      bs,     16);
        cp16(bDst0 + off + 16, bs + 8, 16);
        cp_commit();
    }

    int slot = 0;                      // slab c lives in stage slot (c % 3)
    for (int c = 0; c < NC; c++) {
        cp_wait<1>();                  // slab c landed (c+1 may be in flight)
        __syncthreads();               // releases buffer (c-1)%3 for reuse

        // prefetch slab c+2 into slot (c+2)%3  (the buffer just released)
        if (c + 2 < NC) {
            int ps = slot + 2; if (ps >= NSTAGE) ps -= NSTAGE;
            uint32_t off = (uint32_t)ps * STAGE_B;
            const __half* as = aRow + (c + 2) * BKH;
            const __half* bs = bRow + (c + 2) * BKH;
            cp16(aDst0 + off,      as,     asz);
            cp16(aDst0 + off + 16, as + 8, asz);
            cp16(bDst0 + off,      bs,     16);
            cp16(bDst0 + off + 16, bs + 8, 16);
            cp_commit();
        }

        // ---- compute slab c: two k16 steps ----
        uint32_t aB = aLdBase + (uint32_t)slot * STAGE_B;
        uint32_t bB = bLdBase + (uint32_t)slot * STAGE_B;
#pragma unroll
        for (int kk = 0; kk < 2; kk++) {
            uint32_t kB = (uint32_t)kk * 32;
            uint32_t af[4][4], bf4[2][4];
#pragma unroll
            for (int mi = 0; mi < 4; mi++)
                ldsm_x4(af[mi][0], af[mi][1], af[mi][2], af[mi][3],
                        aB + kB + (uint32_t)mi * (16 * SROWB));
#pragma unroll
            for (int nj = 0; nj < 2; nj++)
                ldsm_x4(bf4[nj][0], bf4[nj][1], bf4[nj][2], bf4[nj][3],
                        bB + kB + (uint32_t)nj * (16 * SROWB));
#pragma unroll
            for (int mi = 0; mi < 4; mi++)
#pragma unroll
                for (int ni = 0; ni < 4; ni++)
                    mma_f16(acc[mi][ni], af[mi], &bf4[ni >> 1][(ni & 1) * 2]);
        }
        if (++slot >= NSTAGE) slot = 0;
    }

    // ---- epilogue ----
    const float* be = bias + (size_t)e * NDIM;
#pragma unroll
    for (int mi = 0; mi < 4; mi++) {
#pragma unroll
        for (int ri = 0; ri < 2; ri++) {
            int r = r0 + wm + mi * 16 + gidl + ri * 8;
            if (r >= r1) continue;
            float sc = FIRST ? 1.f : g_wgt[r];
#pragma unroll
            for (int ni = 0; ni < 4; ni++) {
                int cc = n0 + wn + ni * 8 + 2 * tg;
                float v0 = acc[mi][ni][ri * 2 + 0] + be[cc];
                float v1 = acc[mi][ni][ri * 2 + 1] + be[cc + 1];
                if (FIRST) {
                    v0 = fmaxf(v0, 0.f);
                    v1 = fmaxf(v1, 0.f);
                    *reinterpret_cast<__half2*>(g_h + (size_t)r * NDIM + cc) =
                        __floats2half2_rn(v0, v1);
                } else {
                    v0 *= sc; v1 *= sc;
                    *reinterpret_cast<float2*>(g_z + (size_t)r * NDIM + cc) =
                        make_float2(v0, v1);
                }
            }
        }
    }
}

// ---------------- combine ----------------
__global__ void combine_kernel(float4* __restrict__ out) {
    int i = blockIdx.x * blockDim.x + threadIdx.x;
    const int C4 = DOUT / 4;
    int t = i / C4;
    int c = i % C4;
    int ra = g_rowOf[2 * t + 0];
    int rb = g_rowOf[2 * t + 1];
    const float4* z4 = (const float4*)g_z;
    float4 a = z4[(size_t)ra * C4 + c];
    float4 b = z4[(size_t)rb * C4 + c];
    out[i] = make_float4(a.x + b.x, a.y + b.y, a.z + b.z, a.w + b.w);
}

// ---------------- launch ----------------
extern "C" void kernel_launch(void* const* d_in, const int* in_sizes, int n_in,
                              void* d_out, int out_size) {
    const float* x     = (const float*)d_in[0];
    const float* spike = (const float*)d_in[1];
    const float* Wr    = (const float*)d_in[2];
    const float* br    = (const float*)d_in[3];
    const float* W1    = (const float*)d_in[4];
    const float* b1    = (const float*)d_in[5];
    const float* W2    = (const float*)d_in[6];
    const float* b2    = (const float*)d_in[7];
    float* out = (float*)d_out;

    cudaFuncSetAttribute(gemm_kernel<true>,
                         cudaFuncAttributeMaxDynamicSharedMemorySize, DYN_SMEM);
    cudaFuncSetAttribute(gemm_kernel<false>,
                         cudaFuncAttributeMaxDynamicSharedMemorySize, DYN_SMEM);

    zero_kernel<<<1, 32>>>();
    router_kernel<<<BTOK / 8, 256>>>(x, spike, Wr, br);
    offsets_kernel<<<1, 1>>>();
    scatter_kernel<<<NPAIRS / 256, 256>>>();
    cvtx_kernel<<<(BTOK * DIN / 4) / 256, 256>>>((const float4*)x);
    transpose_kernel<true><<<dim3(DIN / 32, DHID / 32, TOT_E), dim3(32, 8)>>>(W1, DIN, DHID);
    transpose_kernel<false><<<dim3(DHID / 32, DOUT / 32, TOT_E), dim3(32, 8)>>>(W2, DHID, DOUT);

    gemm_kernel<true><<<dim3(MAX_TILES, DHID / BN), 256, DYN_SMEM>>>(b1);
    gemm_kernel<false><<<dim3(MAX_TILES, DOUT / BN), 256, DYN_SMEM>>>(b2);

    combine_kernel<<<(BTOK * DOUT / 4) / 256, 256>>>((float4*)out);
}